// round 4
// baseline (speedup 1.0000x reference)
#include <cuda_runtime.h>

// Problem constants
#define Tn 512
#define Bn 8
#define Hn 256
#define Vn 32000
#define Ln 3
#define Mn (Tn*Bn)   // 4096
#define BH (Bn*Hn)   // 2048

#define NBLK 148     // persistent grid (<= SM count; all co-resident)
#define TILES 256    // 64 m-tiles x 4 n-tiles for the 4096x256 GEMMs

// Scratch (device globals; allocation forbidden in kernel_launch)
__device__ float g_cur[Mn*Hn];
__device__ float g_spk[Mn*Hn];
__device__ float g_h  [Mn*Hn];
__device__ int   g_fcur[Mn];
__device__ int   g_fs  [Mn];
__device__ int   g_fh  [Mn];

// grid-barrier state (zero-init; reset protocol restores zeros every run)
__device__ unsigned g_bin [8];
__device__ unsigned g_bout[8];

// ---- packed fp32x2 helpers (Blackwell FFMA2) --------------------------------
__device__ __forceinline__ unsigned long long pack2(float lo, float hi) {
    unsigned long long r;
    asm("mov.b64 %0, {%1, %2};" : "=l"(r) : "f"(lo), "f"(hi));
    return r;
}
__device__ __forceinline__ void fma2(unsigned long long& d,
                                     unsigned long long a,
                                     unsigned long long b) {
    asm("fma.rn.f32x2 %0, %1, %2, %0;" : "+l"(d) : "l"(a), "l"(b));
}
__device__ __forceinline__ float2 unpack2(unsigned long long v) {
    float2 f;
    asm("mov.b64 {%0, %1}, %2;" : "=f"(f.x), "=f"(f.y) : "l"(v));
    return f;
}

#define MT 64
#define NT 64
#define KT 16

// shared-memory union: GEMM staging vs scan state
struct GS { float As[MT][KT + 1]; float Ws[KT][NT + 4]; int sflag[MT]; };
struct SS { float S[8][32]; float Carry[8][32]; int sel[Tn]; };

// ---- grid barrier -----------------------------------------------------------
__device__ __forceinline__ void gbar(int i) {
    __syncthreads();
    if (threadIdx.x == 0) {
        __threadfence();                         // release prior writes
        atomicAdd(&g_bin[i], 1u);
        while (((volatile unsigned*)g_bin)[i] < (unsigned)NBLK) __nanosleep(64);
        __threadfence();                         // acquire
        unsigned w = atomicAdd(&g_bout[i], 1u);
        if (w == (unsigned)(NBLK - 1)) {         // last one out resets
            ((volatile unsigned*)g_bin)[i] = 0u;
            __threadfence();
            ((volatile unsigned*)g_bout)[i] = 0u;
        }
    }
    __syncthreads();
}

// ---- layer-0 GEMM tile with fused embedding (always dense) ------------------
__device__ __forceinline__ void gemm0_tile(
    int tile,
    const int* __restrict__ tokens,
    const float* __restrict__ tok_emb,
    const float* __restrict__ pos_emb,
    const float* __restrict__ W,
    const float* __restrict__ bias,
    float* __restrict__ C,
    int* __restrict__ fcur, int* __restrict__ fs,
    GS& sm)
{
    const int bm = (tile >> 2) * MT;
    const int bn = (tile & 3) * NT;
    const int tid = threadIdx.x;

    if (tid < MT) sm.sflag[tid] = tokens[bm + tid];     // sflag reused as stok
    if ((tile & 3) == 0 && tid < MT) { fcur[bm + tid] = 1; fs[bm + tid] = 0; }
    __syncthreads();

    const int ty = tid >> 4, tx = tid & 15;
    unsigned long long acc[4][2];
    #pragma unroll
    for (int i = 0; i < 4; i++) { acc[i][0] = 0ull; acc[i][1] = 0ull; }

    const int arow = tid >> 2, akq = (tid & 3) * 4;
    const int wkk = tid >> 4, wnq = (tid & 15) * 4;
    const int at = (bm + arow) >> 3;                    // t = m / B

    for (int k0 = 0; k0 < Hn; k0 += KT) {
        float4 e = *reinterpret_cast<const float4*>(
            &tok_emb[(long long)sm.sflag[arow]*Hn + k0 + akq]);
        float4 p = *reinterpret_cast<const float4*>(&pos_emb[at*Hn + k0 + akq]);
        sm.As[arow][akq + 0] = e.x + p.x;
        sm.As[arow][akq + 1] = e.y + p.y;
        sm.As[arow][akq + 2] = e.z + p.z;
        sm.As[arow][akq + 3] = e.w + p.w;
        float4 w4 = *reinterpret_cast<const float4*>(
            &W[(long long)(k0 + wkk)*Hn + bn + wnq]);
        *reinterpret_cast<float4*>(&sm.Ws[wkk][wnq]) = w4;
        __syncthreads();

        #pragma unroll
        for (int k = 0; k < KT; k++) {
            unsigned long long w01 =
                *reinterpret_cast<const unsigned long long*>(&sm.Ws[k][tx*4]);
            unsigned long long w23 =
                *reinterpret_cast<const unsigned long long*>(&sm.Ws[k][tx*4 + 2]);
            #pragma unroll
            for (int i = 0; i < 4; i++) {
                float a = sm.As[ty*4 + i][k];
                unsigned long long ad = pack2(a, a);
                fma2(acc[i][0], ad, w01);
                fma2(acc[i][1], ad, w23);
            }
        }
        __syncthreads();
    }

    const float b0 = bias[bn + tx*4 + 0];
    const float b1 = bias[bn + tx*4 + 1];
    const float b2 = bias[bn + tx*4 + 2];
    const float b3 = bias[bn + tx*4 + 3];
    #pragma unroll
    for (int i = 0; i < 4; i++) {
        float2 v0 = unpack2(acc[i][0]);
        float2 v1 = unpack2(acc[i][1]);
        float4 o = make_float4(v0.x + b0, v0.y + b1, v1.x + b2, v1.y + b3);
        *reinterpret_cast<float4*>(
            &C[(long long)(bm + ty*4 + i)*Hn + bn + tx*4]) = o;
    }
}

// ---- internal GEMM tile: C = mask(A) @ W + bias, optional ReLU --------------
// flags_in==0 rows are logically zero (possibly unmaterialized).
// Null tile: store relu?(bias) only if biasAny, validity = biasAny.
__device__ __forceinline__ void gemm_tile(
    int tile,
    const float* __restrict__ A,
    const float* __restrict__ W,
    const float* __restrict__ bias,
    float* __restrict__ C,
    int do_relu, int biasAny,
    const int* __restrict__ flags_in,
    int* __restrict__ valid_out,
    int* __restrict__ fs_zero,
    GS& sm)
{
    const int bm = (tile >> 2) * MT;
    const int bn = (tile & 3) * NT;
    const int tid = threadIdx.x;
    const int isbn0 = ((tile & 3) == 0);

    if (tid < MT) sm.sflag[tid] = flags_in[bm + tid];
    if (fs_zero && isbn0 && tid < MT) fs_zero[bm + tid] = 0;
    int anyflag = __syncthreads_or(tid < MT ? sm.sflag[tid] : 0);

    if (!anyflag) {
        if (valid_out && isbn0 && tid < MT) valid_out[bm + tid] = biasAny;
        if (biasAny) {
            int c4 = (tid & 15) * 4;
            int r0 = tid >> 4;
            float4 bv = *reinterpret_cast<const float4*>(&bias[bn + c4]);
            if (do_relu) {
                bv.x = fmaxf(bv.x, 0.0f); bv.y = fmaxf(bv.y, 0.0f);
                bv.z = fmaxf(bv.z, 0.0f); bv.w = fmaxf(bv.w, 0.0f);
            }
            #pragma unroll
            for (int r = r0; r < MT; r += 16)
                *reinterpret_cast<float4*>(&C[(long long)(bm + r)*Hn + bn + c4]) = bv;
        }
        __syncthreads();   // protect sflag reuse by next tile
        return;
    }
    if (valid_out && isbn0 && tid < MT) valid_out[bm + tid] = 1;

    const int ty = tid >> 4, tx = tid & 15;
    unsigned long long acc[4][2];
    #pragma unroll
    for (int i = 0; i < 4; i++) { acc[i][0] = 0ull; acc[i][1] = 0ull; }

    const int arow = tid >> 2, akq = (tid & 3) * 4;
    const int wkk = tid >> 4, wnq = (tid & 15) * 4;

    for (int k0 = 0; k0 < Hn; k0 += KT) {
        float4 a4 = *reinterpret_cast<const float4*>(
            &A[(long long)(bm + arow)*Hn + k0 + akq]);
        if (!sm.sflag[arow]) { a4.x = a4.y = a4.z = a4.w = 0.0f; }
        sm.As[arow][akq + 0] = a4.x; sm.As[arow][akq + 1] = a4.y;
        sm.As[arow][akq + 2] = a4.z; sm.As[arow][akq + 3] = a4.w;
        float4 w4 = *reinterpret_cast<const float4*>(
            &W[(long long)(k0 + wkk)*Hn + bn + wnq]);
        *reinterpret_cast<float4*>(&sm.Ws[wkk][wnq]) = w4;
        __syncthreads();

        #pragma unroll
        for (int k = 0; k < KT; k++) {
            unsigned long long w01 =
                *reinterpret_cast<const unsigned long long*>(&sm.Ws[k][tx*4]);
            unsigned long long w23 =
                *reinterpret_cast<const unsigned long long*>(&sm.Ws[k][tx*4 + 2]);
            #pragma unroll
            for (int i = 0; i < 4; i++) {
                float a = sm.As[ty*4 + i][k];
                unsigned long long ad = pack2(a, a);
                fma2(acc[i][0], ad, w01);
                fma2(acc[i][1], ad, w23);
            }
        }
        __syncthreads();
    }

    const float b0 = bias[bn + tx*4 + 0];
    const float b1 = bias[bn + tx*4 + 1];
    const float b2 = bias[bn + tx*4 + 2];
    const float b3 = bias[bn + tx*4 + 3];
    #pragma unroll
    for (int i = 0; i < 4; i++) {
        float2 v0 = unpack2(acc[i][0]);
        float2 v1 = unpack2(acc[i][1]);
        float4 o = make_float4(v0.x + b0, v0.y + b1, v1.x + b2, v1.y + b3);
        if (do_relu) {
            o.x = fmaxf(o.x, 0.0f); o.y = fmaxf(o.y, 0.0f);
            o.z = fmaxf(o.z, 0.0f); o.w = fmaxf(o.w, 0.0f);
        }
        *reinterpret_cast<float4*>(
            &C[(long long)(bm + ty*4 + i)*Hn + bn + tx*4]) = o;
    }
}

// ---- scan phase: blocks 0..63 each own 32 (b,h) lanes; 8 chunks x 64 steps --
__device__ __forceinline__ void scan_phase(
    const float* __restrict__ cur,
    const float* __restrict__ beta,
    float* __restrict__ spk,
    const int* __restrict__ fcur,
    int* __restrict__ fs,
    SS& sm)
{
    const int blk = blockIdx.x;
    if (blk >= BH / 32) return;                 // 64 active blocks
    const int tid = threadIdx.x;
    const int w = tid >> 5;                     // chunk 0..7
    const int l = tid & 31;
    const int lane = blk * 32 + l;
    const int b = lane >> 8;                    // H = 256
    const int hc = lane & (Hn - 1);

    sm.sel[tid]       = fcur[tid * Bn + b];
    sm.sel[tid + 256] = fcur[(tid + 256) * Bn + b];
    int any = __syncthreads_or(sm.sel[tid] | sm.sel[tid + 256]);
    if (!any) return;                           // fs pre-zeroed upstream

    const float bt = beta[hc];
    const float* base = cur + (long long)(w * 64) * BH + lane;

    float m = 0.0f;
    #pragma unroll 8
    for (int j = 0; j < 64; j++) {
        float c = sm.sel[w*64 + j] ? base[j * BH] : 0.0f;
        m = fmaf(bt, m, c);
    }
    sm.S[w][l] = m;
    __syncthreads();

    if (w == 0) {
        float p = bt;
        #pragma unroll
        for (int q = 0; q < 6; q++) p = p * p;  // beta^64
        float c = 0.0f;
        #pragma unroll
        for (int k = 0; k < 8; k++) {
            sm.Carry[k][l] = c;
            c = fmaf(p, c, sm.S[k][l]);
        }
    }
    __syncthreads();

    m = sm.Carry[w][l];
    #pragma unroll 8
    for (int j = 0; j < 64; j++) {
        int t = w*64 + j;
        float c = sm.sel[t] ? base[j * BH] : 0.0f;
        m = fmaf(bt, m, c);
        float s = (m > 1.0f) ? 1.0f : 0.0f;
        spk[(long long)t * BH + lane] = s;
        if (s != 0.0f) atomicOr(&fs[t * Bn + b], 1);
    }
}

// ---- persistent front kernel: all layers, grid-barrier separated ------------
__global__ void __launch_bounds__(256, 1)
front_kernel(const int* __restrict__ tokens,
             const float* __restrict__ tok_emb,
             const float* __restrict__ pos_emb,
             const float* __restrict__ Wq,
             const float* __restrict__ bq,
             const float* __restrict__ beta,
             const float* __restrict__ Wfc,
             const float* __restrict__ bfc)
{
    __shared__ union USM { GS g; SS s; } sm;
    const int tid = threadIdx.x;

    float* cur = g_cur; float* spk = g_spk; float* h = g_h;
    int* fcur = g_fcur; int* fs = g_fs; int* fh = g_fh;

    // P0: embed + q0 (dense); also fcur=1, fs=0
    for (int t = blockIdx.x; t < TILES; t += NBLK)
        gemm0_tile(t, tokens, tok_emb, pos_emb, Wq, bq, cur, fcur, fs, sm.g);
    gbar(0);

    // P1: scan layer 0
    scan_phase(cur, beta, spk, fcur, fs, sm.s);
    gbar(1);

    // P2: fc0
    {
        const float* bias = bfc;
        int ba = __syncthreads_or(bias[tid] != 0.0f);
        for (int t = blockIdx.x; t < TILES; t += NBLK)
            gemm_tile(t, spk, Wfc, bias, h, 1, ba, fs, fh, nullptr, sm.g);
    }
    gbar(2);

    int bi = 3;
    for (int l = 1; l < Ln; l++) {
        // q_l : cur = mask(h) @ Wq_l + bq_l ; valid->fcur ; zero fs
        {
            const float* bias = bq + l*Hn;
            int ba = __syncthreads_or(bias[tid] != 0.0f);
            for (int t = blockIdx.x; t < TILES; t += NBLK)
                gemm_tile(t, h, Wq + (long long)l*Hn*Hn, bias, cur, 0, ba,
                          fh, fcur, fs, sm.g);
        }
        gbar(bi++);
        // scan_l
        scan_phase(cur, beta + l*Hn, spk, fcur, fs, sm.s);
        gbar(bi++);
        // fc_l : h = relu(mask(spk) @ Wfc_l + bfc_l) ; valid->fh
        {
            const float* bias = bfc + l*Hn;
            int ba = __syncthreads_or(bias[tid] != 0.0f);
            for (int t = blockIdx.x; t < TILES; t += NBLK)
                gemm_tile(t, spk, Wfc + (long long)l*Hn*Hn, bias, h, 1, ba,
                          fs, fh, nullptr, sm.g);
        }
        if (l < Ln - 1) gbar(bi++);
    }
}

// ---- vocab GEMM (output, always stores) --------------------------------------
#define NTV 256
__global__ void __launch_bounds__(256)
vocab_kernel(const float* __restrict__ A,
             const float* __restrict__ W,
             const float* __restrict__ bias,
             float* __restrict__ C,
             const int* __restrict__ flags_in) {
    __shared__ int sflag[MT];
    const int bm = blockIdx.y * MT;
    const int bn = blockIdx.x * NTV;
    const int tid = threadIdx.x;

    if (tid < MT) sflag[tid] = flags_in[bm + tid];
    int anyflag = __syncthreads_or(tid < MT ? sflag[tid] : 0);

    if (!anyflag) {
        int c4 = (tid & 63) * 4;
        int r0 = tid >> 6;
        float4 bv = *reinterpret_cast<const float4*>(&bias[bn + c4]);
        #pragma unroll
        for (int r = r0; r < MT; r += 4)
            __stwt(reinterpret_cast<float4*>(&C[(long long)(bm + r)*Vn + bn + c4]), bv);
        return;
    }

    // dense fallback
    __shared__ __align__(16) float As[MT][KT + 1];
    __shared__ __align__(16) float Ws[KT][NTV + 4];

    const int ty = tid >> 4;
    const int tx = tid & 15;
    float acc[4][16];
    #pragma unroll
    for (int i = 0; i < 4; i++)
        #pragma unroll
        for (int j = 0; j < 16; j++) acc[i][j] = 0.0f;

    for (int k0 = 0; k0 < Hn; k0 += KT) {
        {
            int row = tid >> 2, kq = (tid & 3) * 4;
            float4 a4 = *reinterpret_cast<const float4*>(&A[(long long)(bm + row)*Hn + k0 + kq]);
            if (!sflag[row]) { a4.x = a4.y = a4.z = a4.w = 0.0f; }
            As[row][kq + 0] = a4.x; As[row][kq + 1] = a4.y;
            As[row][kq + 2] = a4.z; As[row][kq + 3] = a4.w;
        }
        #pragma unroll
        for (int it = 0; it < 4; it++) {
            int f = tid + it * 256;
            int kk = f >> 6;
            int nq = (f & 63) * 4;
            float4 w4 = *reinterpret_cast<const float4*>(&W[(long long)(k0 + kk)*Vn + bn + nq]);
            *reinterpret_cast<float4*>(&Ws[kk][nq]) = w4;
        }
        __syncthreads();

        #pragma unroll
        for (int k = 0; k < KT; k++) {
            float a0 = As[ty*4 + 0][k];
            float a1 = As[ty*4 + 1][k];
            float a2 = As[ty*4 + 2][k];
            float a3 = As[ty*4 + 3][k];
            #pragma unroll
            for (int jq = 0; jq < 4; jq++) {
                float4 wq = *reinterpret_cast<const float4*>(&Ws[k][tx*16 + jq*4]);
                float wv[4] = {wq.x, wq.y, wq.z, wq.w};
                #pragma unroll
                for (int j = 0; j < 4; j++) {
                    acc[0][jq*4 + j] = fmaf(a0, wv[j], acc[0][jq*4 + j]);
                    acc[1][jq*4 + j] = fmaf(a1, wv[j], acc[1][jq*4 + j]);
                    acc[2][jq*4 + j] = fmaf(a2, wv[j], acc[2][jq*4 + j]);
                    acc[3][jq*4 + j] = fmaf(a3, wv[j], acc[3][jq*4 + j]);
                }
            }
        }
        __syncthreads();
    }

    #pragma unroll
    for (int i = 0; i < 4; i++) {
        int row = bm + ty*4 + i;
        #pragma unroll
        for (int jq = 0; jq < 4; jq++) {
            float4 o;
            o.x = acc[i][jq*4 + 0] + bias[bn + tx*16 + jq*4 + 0];
            o.y = acc[i][jq*4 + 1] + bias[bn + tx*16 + jq*4 + 1];
            o.z = acc[i][jq*4 + 2] + bias[bn + tx*16 + jq*4 + 2];
            o.w = acc[i][jq*4 + 3] + bias[bn + tx*16 + jq*4 + 3];
            *reinterpret_cast<float4*>(&C[(long long)row*Vn + bn + tx*16 + jq*4]) = o;
        }
    }
}

// ---------------------------------------------------------------------------
// launch
// ---------------------------------------------------------------------------
extern "C" void kernel_launch(void* const* d_in, const int* in_sizes, int n_in,
                              void* d_out, int out_size) {
    const int*   tokens  = (const int*)  d_in[0];
    const float* tok_emb = (const float*)d_in[1];
    const float* pos_emb = (const float*)d_in[2];
    const float* Wq      = (const float*)d_in[3];
    const float* bq      = (const float*)d_in[4];
    const float* beta    = (const float*)d_in[5];
    const float* Wfc     = (const float*)d_in[6];
    const float* bfc     = (const float*)d_in[7];
    const float* Wout    = (const float*)d_in[8];
    const float* bout    = (const float*)d_in[9];
    float* out = (float*)d_out;

    float *h; int *fh;
    cudaGetSymbolAddress((void**)&h,  g_h);
    cudaGetSymbolAddress((void**)&fh, g_fh);

    front_kernel<<<NBLK, 256>>>(tokens, tok_emb, pos_emb, Wq, bq, beta, Wfc, bfc);

    dim3 gbig(Vn / NTV, Mn / MT);    // (125, 64)
    vocab_kernel<<<gbig, 256>>>(h, Wout, bout, out, fh);
}

// round 5
// speedup vs baseline: 1.0741x; 1.0741x over previous
#include <cuda_runtime.h>

// Problem constants
#define Tn 512
#define Bn 8
#define Hn 256
#define Vn 32000
#define Ln 3
#define Mn (Tn*Bn)   // 4096
#define BH (Bn*Hn)   // 2048

#define TBLK 64      // tail persistent grid (1 block/SM, cheap barriers)
#define TILES 256    // 64 m-tiles x 4 n-tiles for 4096x256 GEMMs

// Scratch (device globals; allocation forbidden in kernel_launch)
__device__ float g_cur[Mn*Hn];
__device__ float g_spk[Mn*Hn];
__device__ float g_h  [Mn*Hn];
__device__ int   g_fcur[Mn];
__device__ int   g_fs  [Mn];
__device__ int   g_fh  [Mn];

// grid-barrier state (zero-init; last-out reset keeps it reusable per replay)
__device__ unsigned g_bin [8];
__device__ unsigned g_bout[8];

// ---- packed fp32x2 helpers (Blackwell FFMA2) --------------------------------
__device__ __forceinline__ unsigned long long pack2(float lo, float hi) {
    unsigned long long r;
    asm("mov.b64 %0, {%1, %2};" : "=l"(r) : "f"(lo), "f"(hi));
    return r;
}
__device__ __forceinline__ void fma2(unsigned long long& d,
                                     unsigned long long a,
                                     unsigned long long b) {
    asm("fma.rn.f32x2 %0, %1, %2, %0;" : "+l"(d) : "l"(a), "l"(b));
}
__device__ __forceinline__ float2 unpack2(unsigned long long v) {
    float2 f;
    asm("mov.b64 {%0, %1}, %2;" : "=f"(f.x), "=f"(f.y) : "l"(v));
    return f;
}

#define MT 64
#define NT 64
#define KT 16

struct GS { float As[MT][KT + 1]; float Ws[KT][NT + 4]; int sflag[MT]; };
struct SS { float S[8][32]; float Carry[8][32]; int sel[Tn]; };

// ---- grid barrier (TBLK arrivals) -------------------------------------------
__device__ __forceinline__ void gbar(int i) {
    __syncthreads();
    if (threadIdx.x == 0) {
        __threadfence();
        atomicAdd(&g_bin[i], 1u);
        while (((volatile unsigned*)g_bin)[i] < (unsigned)TBLK) __nanosleep(32);
        __threadfence();
        unsigned w = atomicAdd(&g_bout[i], 1u);
        if (w == (unsigned)(TBLK - 1)) {
            ((volatile unsigned*)g_bin)[i] = 0u;
            __threadfence();
            ((volatile unsigned*)g_bout)[i] = 0u;
        }
    }
    __syncthreads();
}

// ---------------------------------------------------------------------------
// Layer-0 q-GEMM with fused embedding (separate launch; dense; FFMA2).
// Also: fcur=1 for all rows, fs=0.
// ---------------------------------------------------------------------------
__global__ void __launch_bounds__(256)
gemm_embed_kernel(const int* __restrict__ tokens,
                  const float* __restrict__ tok_emb,
                  const float* __restrict__ pos_emb,
                  const float* __restrict__ W,
                  const float* __restrict__ bias,
                  float* __restrict__ C,
                  int* __restrict__ fcur,
                  int* __restrict__ fs_zero) {
    __shared__ __align__(16) float As[MT][KT + 1];
    __shared__ __align__(16) float Ws[KT][NT + 4];
    __shared__ int stok[MT];

    const int bm = blockIdx.y * MT;
    const int bn = blockIdx.x * NT;
    const int tid = threadIdx.x;

    if (tid < MT) stok[tid] = tokens[bm + tid];
    if (blockIdx.x == 0 && tid < MT) {
        fcur[bm + tid] = 1;
        fs_zero[bm + tid] = 0;
    }
    __syncthreads();

    const int ty = tid >> 4, tx = tid & 15;
    unsigned long long acc[4][2];
    #pragma unroll
    for (int i = 0; i < 4; i++) { acc[i][0] = 0ull; acc[i][1] = 0ull; }

    const int arow = tid >> 2, akq = (tid & 3) * 4;
    const int wkk = tid >> 4, wnq = (tid & 15) * 4;
    const int at = (bm + arow) >> 3;   // t = m / B

    for (int k0 = 0; k0 < Hn; k0 += KT) {
        float4 e = *reinterpret_cast<const float4*>(
            &tok_emb[(long long)stok[arow]*Hn + k0 + akq]);
        float4 p = *reinterpret_cast<const float4*>(&pos_emb[at*Hn + k0 + akq]);
        As[arow][akq + 0] = e.x + p.x;
        As[arow][akq + 1] = e.y + p.y;
        As[arow][akq + 2] = e.z + p.z;
        As[arow][akq + 3] = e.w + p.w;
        float4 w4 = *reinterpret_cast<const float4*>(
            &W[(long long)(k0 + wkk)*Hn + bn + wnq]);
        *reinterpret_cast<float4*>(&Ws[wkk][wnq]) = w4;
        __syncthreads();

        #pragma unroll
        for (int k = 0; k < KT; k++) {
            unsigned long long w01 =
                *reinterpret_cast<const unsigned long long*>(&Ws[k][tx*4]);
            unsigned long long w23 =
                *reinterpret_cast<const unsigned long long*>(&Ws[k][tx*4 + 2]);
            #pragma unroll
            for (int i = 0; i < 4; i++) {
                float a = As[ty*4 + i][k];
                unsigned long long ad = pack2(a, a);
                fma2(acc[i][0], ad, w01);
                fma2(acc[i][1], ad, w23);
            }
        }
        __syncthreads();
    }

    const float b0 = bias[bn + tx*4 + 0];
    const float b1 = bias[bn + tx*4 + 1];
    const float b2 = bias[bn + tx*4 + 2];
    const float b3 = bias[bn + tx*4 + 3];
    #pragma unroll
    for (int i = 0; i < 4; i++) {
        float2 v0 = unpack2(acc[i][0]);
        float2 v1 = unpack2(acc[i][1]);
        float4 o = make_float4(v0.x + b0, v0.y + b1, v1.x + b2, v1.y + b3);
        *reinterpret_cast<float4*>(
            &C[(long long)(bm + ty*4 + i)*Hn + bn + tx*4]) = o;
    }
}

// ---- internal GEMM tile (tail): C = mask(A) @ W + bias, optional ReLU -------
__device__ __forceinline__ void gemm_tile(
    int tile,
    const float* __restrict__ A,
    const float* __restrict__ W,
    const float* __restrict__ bias,
    float* __restrict__ C,
    int do_relu, int biasAny,
    const int* __restrict__ flags_in,
    int* __restrict__ valid_out,
    int* __restrict__ fs_zero,
    GS& sm)
{
    const int bm = (tile >> 2) * MT;
    const int bn = (tile & 3) * NT;
    const int tid = threadIdx.x;
    const int isbn0 = ((tile & 3) == 0);

    if (tid < MT) sm.sflag[tid] = flags_in[bm + tid];
    if (fs_zero && isbn0 && tid < MT) fs_zero[bm + tid] = 0;
    int anyflag = __syncthreads_or(tid < MT ? sm.sflag[tid] : 0);

    if (!anyflag) {
        if (valid_out && isbn0 && tid < MT) valid_out[bm + tid] = biasAny;
        if (biasAny) {
            int c4 = (tid & 15) * 4;
            int r0 = tid >> 4;
            float4 bv = *reinterpret_cast<const float4*>(&bias[bn + c4]);
            if (do_relu) {
                bv.x = fmaxf(bv.x, 0.0f); bv.y = fmaxf(bv.y, 0.0f);
                bv.z = fmaxf(bv.z, 0.0f); bv.w = fmaxf(bv.w, 0.0f);
            }
            #pragma unroll
            for (int r = r0; r < MT; r += 16)
                *reinterpret_cast<float4*>(&C[(long long)(bm + r)*Hn + bn + c4]) = bv;
        }
        __syncthreads();   // protect sflag reuse by next tile
        return;
    }
    if (valid_out && isbn0 && tid < MT) valid_out[bm + tid] = 1;

    const int ty = tid >> 4, tx = tid & 15;
    unsigned long long acc[4][2];
    #pragma unroll
    for (int i = 0; i < 4; i++) { acc[i][0] = 0ull; acc[i][1] = 0ull; }

    const int arow = tid >> 2, akq = (tid & 3) * 4;
    const int wkk = tid >> 4, wnq = (tid & 15) * 4;

    for (int k0 = 0; k0 < Hn; k0 += KT) {
        float4 a4 = *reinterpret_cast<const float4*>(
            &A[(long long)(bm + arow)*Hn + k0 + akq]);
        if (!sm.sflag[arow]) { a4.x = a4.y = a4.z = a4.w = 0.0f; }
        sm.As[arow][akq + 0] = a4.x; sm.As[arow][akq + 1] = a4.y;
        sm.As[arow][akq + 2] = a4.z; sm.As[arow][akq + 3] = a4.w;
        float4 w4 = *reinterpret_cast<const float4*>(
            &W[(long long)(k0 + wkk)*Hn + bn + wnq]);
        *reinterpret_cast<float4*>(&sm.Ws[wkk][wnq]) = w4;
        __syncthreads();

        #pragma unroll
        for (int k = 0; k < KT; k++) {
            unsigned long long w01 =
                *reinterpret_cast<const unsigned long long*>(&sm.Ws[k][tx*4]);
            unsigned long long w23 =
                *reinterpret_cast<const unsigned long long*>(&sm.Ws[k][tx*4 + 2]);
            #pragma unroll
            for (int i = 0; i < 4; i++) {
                float a = sm.As[ty*4 + i][k];
                unsigned long long ad = pack2(a, a);
                fma2(acc[i][0], ad, w01);
                fma2(acc[i][1], ad, w23);
            }
        }
        __syncthreads();
    }

    const float b0 = bias[bn + tx*4 + 0];
    const float b1 = bias[bn + tx*4 + 1];
    const float b2 = bias[bn + tx*4 + 2];
    const float b3 = bias[bn + tx*4 + 3];
    #pragma unroll
    for (int i = 0; i < 4; i++) {
        float2 v0 = unpack2(acc[i][0]);
        float2 v1 = unpack2(acc[i][1]);
        float4 o = make_float4(v0.x + b0, v0.y + b1, v1.x + b2, v1.y + b3);
        if (do_relu) {
            o.x = fmaxf(o.x, 0.0f); o.y = fmaxf(o.y, 0.0f);
            o.z = fmaxf(o.z, 0.0f); o.w = fmaxf(o.w, 0.0f);
        }
        *reinterpret_cast<float4*>(
            &C[(long long)(bm + ty*4 + i)*Hn + bn + tx*4]) = o;
    }
}

// ---- scan phase (tail): 64 blocks x 32 lanes; 8 chunks x 64 steps ----------
__device__ __forceinline__ void scan_phase(
    const float* __restrict__ cur,
    const float* __restrict__ beta,
    float* __restrict__ spk,
    const int* __restrict__ fcur,
    int* __restrict__ fs,
    SS& sm)
{
    const int blk = blockIdx.x;
    const int tid = threadIdx.x;
    const int w = tid >> 5;                 // chunk 0..7
    const int l = tid & 31;
    const int lane = blk * 32 + l;
    const int b = lane >> 8;                // H = 256
    const int hc = lane & (Hn - 1);

    sm.sel[tid]       = fcur[tid * Bn + b];
    sm.sel[tid + 256] = fcur[(tid + 256) * Bn + b];
    int any = __syncthreads_or(sm.sel[tid] | sm.sel[tid + 256]);
    if (!any) return;                       // fs pre-zeroed upstream

    const float bt = beta[hc];
    const float* base = cur + (long long)(w * 64) * BH + lane;

    float m = 0.0f;
    #pragma unroll 8
    for (int j = 0; j < 64; j++) {
        float c = sm.sel[w*64 + j] ? base[j * BH] : 0.0f;
        m = fmaf(bt, m, c);
    }
    sm.S[w][l] = m;
    __syncthreads();

    if (w == 0) {
        float p = bt;
        #pragma unroll
        for (int q = 0; q < 6; q++) p = p * p;   // beta^64
        float c = 0.0f;
        #pragma unroll
        for (int k = 0; k < 8; k++) {
            sm.Carry[k][l] = c;
            c = fmaf(p, c, sm.S[k][l]);
        }
    }
    __syncthreads();

    m = sm.Carry[w][l];
    #pragma unroll 8
    for (int j = 0; j < 64; j++) {
        int t = w*64 + j;
        float c = sm.sel[t] ? base[j * BH] : 0.0f;
        m = fmaf(bt, m, c);
        float s = (m > 1.0f) ? 1.0f : 0.0f;
        spk[(long long)t * BH + lane] = s;
        if (s != 0.0f) atomicOr(&fs[t * Bn + b], 1);
    }
}

// ---- persistent tail: scan0 .. fc2 with 7 grid barriers ---------------------
__global__ void __launch_bounds__(256, 1)
tail_kernel(const float* __restrict__ Wq,
            const float* __restrict__ bq,
            const float* __restrict__ beta,
            const float* __restrict__ Wfc,
            const float* __restrict__ bfc)
{
    __shared__ union USM { GS g; SS s; } sm;
    const int tid = threadIdx.x;

    float* cur = g_cur; float* spk = g_spk; float* h = g_h;
    int* fcur = g_fcur; int* fs = g_fs; int* fh = g_fh;

    // P0: scan layer 0 (fcur=1, fs=0 set by gemm_embed)
    scan_phase(cur, beta, spk, fcur, fs, sm.s);
    gbar(0);

    // P1: fc0  h = relu(mask(spk) @ Wfc0 + bfc0); valid->fh
    {
        const float* bias = bfc;
        int ba = __syncthreads_or(bias[tid] != 0.0f);
        for (int t = blockIdx.x; t < TILES; t += TBLK)
            gemm_tile(t, spk, Wfc, bias, h, 1, ba, fs, fh, nullptr, sm.g);
    }
    gbar(1);

    int bi = 2;
    for (int l = 1; l < Ln; l++) {
        // q_l : cur = mask(h) @ Wq_l + bq_l ; valid->fcur ; zero fs
        {
            const float* bias = bq + l*Hn;
            int ba = __syncthreads_or(bias[tid] != 0.0f);
            for (int t = blockIdx.x; t < TILES; t += TBLK)
                gemm_tile(t, h, Wq + (long long)l*Hn*Hn, bias, cur, 0, ba,
                          fh, fcur, fs, sm.g);
        }
        gbar(bi++);
        // scan_l
        scan_phase(cur, beta + l*Hn, spk, fcur, fs, sm.s);
        gbar(bi++);
        // fc_l
        {
            const float* bias = bfc + l*Hn;
            int ba = __syncthreads_or(bias[tid] != 0.0f);
            for (int t = blockIdx.x; t < TILES; t += TBLK)
                gemm_tile(t, spk, Wfc + (long long)l*Hn*Hn, bias, h, 1, ba,
                          fs, fh, nullptr, sm.g);
        }
        if (l < Ln - 1) gbar(bi++);
    }
}

// ---- vocab GEMM (output, always stores) -------------------------------------
#define NTV 256
__global__ void __launch_bounds__(256)
vocab_kernel(const float* __restrict__ A,
             const float* __restrict__ W,
             const float* __restrict__ bias,
             float* __restrict__ C,
             const int* __restrict__ flags_in) {
    __shared__ int sflag[MT];
    const int bm = blockIdx.y * MT;
    const int bn = blockIdx.x * NTV;
    const int tid = threadIdx.x;

    if (tid < MT) sflag[tid] = flags_in[bm + tid];
    int anyflag = __syncthreads_or(tid < MT ? sflag[tid] : 0);

    if (!anyflag) {
        int c4 = (tid & 63) * 4;
        int r0 = tid >> 6;
        float4 bv = *reinterpret_cast<const float4*>(&bias[bn + c4]);
        #pragma unroll
        for (int r = r0; r < MT; r += 4)
            __stwt(reinterpret_cast<float4*>(&C[(long long)(bm + r)*Vn + bn + c4]), bv);
        return;
    }

    // dense fallback
    __shared__ __align__(16) float As[MT][KT + 1];
    __shared__ __align__(16) float Ws[KT][NTV + 4];

    const int ty = tid >> 4;
    const int tx = tid & 15;
    float acc[4][16];
    #pragma unroll
    for (int i = 0; i < 4; i++)
        #pragma unroll
        for (int j = 0; j < 16; j++) acc[i][j] = 0.0f;

    for (int k0 = 0; k0 < Hn; k0 += KT) {
        {
            int row = tid >> 2, kq = (tid & 3) * 4;
            float4 a4 = *reinterpret_cast<const float4*>(&A[(long long)(bm + row)*Hn + k0 + kq]);
            if (!sflag[row]) { a4.x = a4.y = a4.z = a4.w = 0.0f; }
            As[row][kq + 0] = a4.x; As[row][kq + 1] = a4.y;
            As[row][kq + 2] = a4.z; As[row][kq + 3] = a4.w;
        }
        #pragma unroll
        for (int it = 0; it < 4; it++) {
            int f = tid + it * 256;
            int kk = f >> 6;
            int nq = (f & 63) * 4;
            float4 w4 = *reinterpret_cast<const float4*>(&W[(long long)(k0 + kk)*Vn + bn + nq]);
            *reinterpret_cast<float4*>(&Ws[kk][nq]) = w4;
        }
        __syncthreads();

        #pragma unroll
        for (int k = 0; k < KT; k++) {
            float a0 = As[ty*4 + 0][k];
            float a1 = As[ty*4 + 1][k];
            float a2 = As[ty*4 + 2][k];
            float a3 = As[ty*4 + 3][k];
            #pragma unroll
            for (int jq = 0; jq < 4; jq++) {
                float4 wq = *reinterpret_cast<const float4*>(&Ws[k][tx*16 + jq*4]);
                float wv[4] = {wq.x, wq.y, wq.z, wq.w};
                #pragma unroll
                for (int j = 0; j < 4; j++) {
                    acc[0][jq*4 + j] = fmaf(a0, wv[j], acc[0][jq*4 + j]);
                    acc[1][jq*4 + j] = fmaf(a1, wv[j], acc[1][jq*4 + j]);
                    acc[2][jq*4 + j] = fmaf(a2, wv[j], acc[2][jq*4 + j]);
                    acc[3][jq*4 + j] = fmaf(a3, wv[j], acc[3][jq*4 + j]);
                }
            }
        }
        __syncthreads();
    }

    #pragma unroll
    for (int i = 0; i < 4; i++) {
        int row = bm + ty*4 + i;
        #pragma unroll
        for (int jq = 0; jq < 4; jq++) {
            float4 o;
            o.x = acc[i][jq*4 + 0] + bias[bn + tx*16 + jq*4 + 0];
            o.y = acc[i][jq*4 + 1] + bias[bn + tx*16 + jq*4 + 1];
            o.z = acc[i][jq*4 + 2] + bias[bn + tx*16 + jq*4 + 2];
            o.w = acc[i][jq*4 + 3] + bias[bn + tx*16 + jq*4 + 3];
            *reinterpret_cast<float4*>(&C[(long long)row*Vn + bn + tx*16 + jq*4]) = o;
        }
    }
}

// ---------------------------------------------------------------------------
// launch
// ---------------------------------------------------------------------------
extern "C" void kernel_launch(void* const* d_in, const int* in_sizes, int n_in,
                              void* d_out, int out_size) {
    const int*   tokens  = (const int*)  d_in[0];
    const float* tok_emb = (const float*)d_in[1];
    const float* pos_emb = (const float*)d_in[2];
    const float* Wq      = (const float*)d_in[3];
    const float* bq      = (const float*)d_in[4];
    const float* beta    = (const float*)d_in[5];
    const float* Wfc     = (const float*)d_in[6];
    const float* bfc     = (const float*)d_in[7];
    const float* Wout    = (const float*)d_in[8];
    const float* bout    = (const float*)d_in[9];
    float* out = (float*)d_out;

    float *cur, *h; int *fcur, *fs, *fh;
    cudaGetSymbolAddress((void**)&cur,  g_cur);
    cudaGetSymbolAddress((void**)&h,    g_h);
    cudaGetSymbolAddress((void**)&fcur, g_fcur);
    cudaGetSymbolAddress((void**)&fs,   g_fs);
    cudaGetSymbolAddress((void**)&fh,   g_fh);

    dim3 gsmall(Hn / NT, Mn / MT);   // (4, 64)
    gemm_embed_kernel<<<gsmall, 256>>>(tokens, tok_emb, pos_emb,
                                       Wq, bq, cur, fcur, fs);

    tail_kernel<<<TBLK, 256>>>(Wq, bq, beta, Wfc, bfc);

    dim3 gbig(Vn / NTV, Mn / MT);    // (125, 64)
    vocab_kernel<<<gbig, 256>>>(h, Wout, bout, out, fh);
}

// round 6
// speedup vs baseline: 1.2063x; 1.1231x over previous
#include <cuda_runtime.h>

// Problem constants
#define Tn 512
#define Bn 8
#define Hn 256
#define Vn 32000
#define Ln 3
#define Mn (Tn*Bn)   // 4096
#define BH (Bn*Hn)   // 2048

// Scratch (device globals; allocation forbidden in kernel_launch)
__device__ float g_cur[Mn*Hn];
__device__ float g_spk[Mn*Hn];
__device__ float g_h  [Mn*Hn];
__device__ int   g_fcur[Mn];
__device__ int   g_fs  [Mn];
__device__ int   g_fh  [Mn];

typedef unsigned long long ULL;

// ---- packed fp32x2 helpers (Blackwell FFMA2) --------------------------------
__device__ __forceinline__ ULL pack2(float lo, float hi) {
    ULL r;
    asm("mov.b64 %0, {%1, %2};" : "=l"(r) : "f"(lo), "f"(hi));
    return r;
}
__device__ __forceinline__ void fma2(ULL& d, ULL a, ULL b) {
    asm("fma.rn.f32x2 %0, %1, %2, %0;" : "+l"(d) : "l"(a), "l"(b));
}
__device__ __forceinline__ float2 unpack2(ULL v) {
    float2 f;
    asm("mov.b64 {%0, %1}, %2;" : "=f"(f.x), "=f"(f.y) : "l"(v));
    return f;
}

#define MT 64
#define NT 64
#define KT 16
#define KT2 32

// ---------------------------------------------------------------------------
// Layer-0 q-GEMM with fused embedding. Dense, FFMA2, row-pair packing.
// Tile 64x64, KT2=32, 128 threads, 8 rows x 4 cols per thread.
// A staged TRANSPOSED (Ast[k][row]) so row-pairs are LDS.128-loadable as
// packed f32x2 operands. Also: fcur=1 for all rows, fs=0 (bn==0 blocks).
// ---------------------------------------------------------------------------
__global__ void __launch_bounds__(128)
gemm_embed_kernel(const int* __restrict__ tokens,
                  const float* __restrict__ tok_emb,
                  const float* __restrict__ pos_emb,
                  const float* __restrict__ W,
                  const float* __restrict__ bias,
                  float* __restrict__ C,
                  int* __restrict__ fcur,
                  int* __restrict__ fs_zero) {
    __shared__ __align__(16) float Ast[KT2][MT + 4];   // [k][row], stride 68
    __shared__ __align__(16) float Ws2[KT2][NT + 4];
    __shared__ int stok[MT];

    const int bm = blockIdx.y * MT;
    const int bn = blockIdx.x * NT;
    const int tid = threadIdx.x;

    if (tid < MT) stok[tid] = tokens[bm + tid];
    if (blockIdx.x == 0 && tid < MT) {
        fcur[bm + tid] = 1;
        fs_zero[bm + tid] = 0;
    }
    __syncthreads();

    const int ty = tid >> 4;   // 0..7  -> 8-row group
    const int tx = tid & 15;   // 0..15 -> 4-col group

    ULL acc[4][4];             // [row-pair][col]
    #pragma unroll
    for (int p = 0; p < 4; p++)
        #pragma unroll
        for (int c = 0; c < 4; c++) acc[p][c] = 0ull;

    for (int k0 = 0; k0 < Hn; k0 += KT2) {
        // stage A transposed: 64 rows x 32 k = 512 float4, 4 per thread
        #pragma unroll
        for (int it = 0; it < 4; it++) {
            int f = tid + it * 128;
            int row = f & 63;
            int kq  = (f >> 6) * 4;
            int m   = bm + row;
            float4 e = *reinterpret_cast<const float4*>(
                &tok_emb[(long long)stok[row]*Hn + k0 + kq]);
            float4 p4 = *reinterpret_cast<const float4*>(
                &pos_emb[(m >> 3)*Hn + k0 + kq]);
            Ast[kq + 0][row] = e.x + p4.x;
            Ast[kq + 1][row] = e.y + p4.y;
            Ast[kq + 2][row] = e.z + p4.z;
            Ast[kq + 3][row] = e.w + p4.w;
        }
        // stage W: 32 k x 64 n = 512 float4, 4 per thread
        #pragma unroll
        for (int it = 0; it < 4; it++) {
            int f = tid + it * 128;
            int kk = f >> 4;
            int nq = (f & 15) * 4;
            *reinterpret_cast<float4*>(&Ws2[kk][nq]) =
                *reinterpret_cast<const float4*>(
                    &W[(long long)(k0 + kk)*Hn + bn + nq]);
        }
        __syncthreads();

        #pragma unroll 8
        for (int k = 0; k < KT2; k++) {
            const ULL* ap = reinterpret_cast<const ULL*>(&Ast[k][ty*8]);
            ULL a0 = ap[0], a1 = ap[1], a2 = ap[2], a3 = ap[3];
            float4 w = *reinterpret_cast<const float4*>(&Ws2[k][tx*4]);
            ULL w0 = pack2(w.x, w.x);
            ULL w1 = pack2(w.y, w.y);
            ULL w2 = pack2(w.z, w.z);
            ULL w3 = pack2(w.w, w.w);
            fma2(acc[0][0], a0, w0); fma2(acc[0][1], a0, w1);
            fma2(acc[0][2], a0, w2); fma2(acc[0][3], a0, w3);
            fma2(acc[1][0], a1, w0); fma2(acc[1][1], a1, w1);
            fma2(acc[1][2], a1, w2); fma2(acc[1][3], a1, w3);
            fma2(acc[2][0], a2, w0); fma2(acc[2][1], a2, w1);
            fma2(acc[2][2], a2, w2); fma2(acc[2][3], a2, w3);
            fma2(acc[3][0], a3, w0); fma2(acc[3][1], a3, w1);
            fma2(acc[3][2], a3, w2); fma2(acc[3][3], a3, w3);
        }
        __syncthreads();
    }

    const float b0 = bias[bn + tx*4 + 0];
    const float b1 = bias[bn + tx*4 + 1];
    const float b2 = bias[bn + tx*4 + 2];
    const float b3 = bias[bn + tx*4 + 3];
    #pragma unroll
    for (int p = 0; p < 4; p++) {
        float2 u0 = unpack2(acc[p][0]);
        float2 u1 = unpack2(acc[p][1]);
        float2 u2 = unpack2(acc[p][2]);
        float2 u3 = unpack2(acc[p][3]);
        int r = bm + ty*8 + p*2;
        float4 o0 = make_float4(u0.x + b0, u1.x + b1, u2.x + b2, u3.x + b3);
        float4 o1 = make_float4(u0.y + b0, u1.y + b1, u2.y + b2, u3.y + b3);
        *reinterpret_cast<float4*>(&C[(long long)r*Hn + bn + tx*4]) = o0;
        *reinterpret_cast<float4*>(&C[(long long)(r+1)*Hn + bn + tx*4]) = o1;
    }
}

// ---------------------------------------------------------------------------
// Internal GEMM (N = Hn): C = mask(A) @ W + bias, optional ReLU.
// flags_in==0 rows are logically zero (may be unmaterialized). Null tile:
// store relu?(bias) only if bias vector nonzero; validity = biasAny.
// ---------------------------------------------------------------------------
__global__ void __launch_bounds__(128)
gemm_internal_kernel(const float* __restrict__ A,
                     const float* __restrict__ W,
                     const float* __restrict__ bias,
                     float* __restrict__ C,
                     int do_relu,
                     const int* __restrict__ flags_in,
                     int* __restrict__ valid_out,
                     int* __restrict__ fs_zero) {
    __shared__ __align__(16) float As[MT][KT + 1];
    __shared__ __align__(16) float Ws[KT][NT + 4];
    __shared__ int sflag[MT];

    const int bm = blockIdx.y * MT;
    const int bn = blockIdx.x * NT;
    const int tid = threadIdx.x;

    if (tid < MT) sflag[tid] = flags_in[bm + tid];
    float bb0 = bias[tid], bb1 = bias[tid + 128];
    int biasAny = __syncthreads_or((bb0 != 0.0f) | (bb1 != 0.0f));
    int anyflag = __syncthreads_or(tid < MT ? sflag[tid] : 0);

    if (fs_zero && blockIdx.x == 0 && tid < MT) fs_zero[bm + tid] = 0;

    if (!anyflag) {
        if (valid_out && blockIdx.x == 0 && tid < MT)
            valid_out[bm + tid] = biasAny;
        if (biasAny) {
            int c4 = (tid & 15) * 4;
            int r0 = tid >> 4;
            float4 bv = *reinterpret_cast<const float4*>(&bias[bn + c4]);
            if (do_relu) {
                bv.x = fmaxf(bv.x, 0.0f); bv.y = fmaxf(bv.y, 0.0f);
                bv.z = fmaxf(bv.z, 0.0f); bv.w = fmaxf(bv.w, 0.0f);
            }
            #pragma unroll
            for (int r = r0; r < MT; r += 8)
                *reinterpret_cast<float4*>(&C[(long long)(bm + r)*Hn + bn + c4]) = bv;
        }
        return;
    }

    if (valid_out && blockIdx.x == 0 && tid < MT) valid_out[bm + tid] = 1;

    // dense path (masked staging)
    const int ty = tid >> 3;
    const int tx = tid & 7;
    float acc[4][8];
    #pragma unroll
    for (int i = 0; i < 4; i++)
        #pragma unroll
        for (int j = 0; j < 8; j++) acc[i][j] = 0.0f;

    for (int k0 = 0; k0 < Hn; k0 += KT) {
        #pragma unroll
        for (int it = 0; it < 2; it++) {
            int f = tid + it * 128;
            int row = f >> 2;
            int kq  = (f & 3) * 4;
            float4 a4 = *reinterpret_cast<const float4*>(&A[(long long)(bm + row)*Hn + k0 + kq]);
            if (!sflag[row]) { a4.x = a4.y = a4.z = a4.w = 0.0f; }
            As[row][kq + 0] = a4.x; As[row][kq + 1] = a4.y;
            As[row][kq + 2] = a4.z; As[row][kq + 3] = a4.w;
        }
        #pragma unroll
        for (int it = 0; it < 2; it++) {
            int f = tid + it * 128;
            int kk = f >> 4;
            int nq = (f & 15) * 4;
            float4 w4 = *reinterpret_cast<const float4*>(&W[(long long)(k0 + kk)*Hn + bn + nq]);
            *reinterpret_cast<float4*>(&Ws[kk][nq]) = w4;
        }
        __syncthreads();

        #pragma unroll
        for (int k = 0; k < KT; k++) {
            float a0 = As[ty*4 + 0][k];
            float a1 = As[ty*4 + 1][k];
            float a2 = As[ty*4 + 2][k];
            float a3 = As[ty*4 + 3][k];
            float4 w0 = *reinterpret_cast<const float4*>(&Ws[k][tx*8]);
            float4 w1 = *reinterpret_cast<const float4*>(&Ws[k][tx*8 + 4]);
            float wv[8] = {w0.x, w0.y, w0.z, w0.w, w1.x, w1.y, w1.z, w1.w};
            #pragma unroll
            for (int j = 0; j < 8; j++) {
                acc[0][j] = fmaf(a0, wv[j], acc[0][j]);
                acc[1][j] = fmaf(a1, wv[j], acc[1][j]);
                acc[2][j] = fmaf(a2, wv[j], acc[2][j]);
                acc[3][j] = fmaf(a3, wv[j], acc[3][j]);
            }
        }
        __syncthreads();
    }

    float bvals[8];
    #pragma unroll
    for (int j = 0; j < 8; j++) bvals[j] = bias[bn + tx*8 + j];

    #pragma unroll
    for (int i = 0; i < 4; i++) {
        int row = bm + ty*4 + i;
        float4 o0, o1;
        o0.x = acc[i][0] + bvals[0]; o0.y = acc[i][1] + bvals[1];
        o0.z = acc[i][2] + bvals[2]; o0.w = acc[i][3] + bvals[3];
        o1.x = acc[i][4] + bvals[4]; o1.y = acc[i][5] + bvals[5];
        o1.z = acc[i][6] + bvals[6]; o1.w = acc[i][7] + bvals[7];
        if (do_relu) {
            o0.x = fmaxf(o0.x, 0.0f); o0.y = fmaxf(o0.y, 0.0f);
            o0.z = fmaxf(o0.z, 0.0f); o0.w = fmaxf(o0.w, 0.0f);
            o1.x = fmaxf(o1.x, 0.0f); o1.y = fmaxf(o1.y, 0.0f);
            o1.z = fmaxf(o1.z, 0.0f); o1.w = fmaxf(o1.w, 0.0f);
        }
        float* cp = &C[(long long)row*Hn + bn + tx*8];
        *reinterpret_cast<float4*>(cp)     = o0;
        *reinterpret_cast<float4*>(cp + 4) = o1;
    }
}

// ---------------------------------------------------------------------------
// Parallel leaky scan + spike. Block = 512 thr = 16 chunks x 32 lanes;
// grid = 64 blocks. Gated by fcur validity flags; early-exit when the whole
// column chunk is logically zero. atomicOr fs on actual spikes.
// ---------------------------------------------------------------------------
#define CHUNKS 16
#define CLEN   32
#define LPB    32

__global__ void __launch_bounds__(512)
scan_kernel(const float* __restrict__ cur,
            const float* __restrict__ beta,
            float* __restrict__ spk,
            const int* __restrict__ fcur,
            int* __restrict__ fs) {
    __shared__ float S[CHUNKS][LPB];
    __shared__ float Carry[CHUNKS][LPB];
    __shared__ int sel[Tn];

    const int tid  = threadIdx.x;
    const int w    = tid >> 5;
    const int l    = tid & 31;
    const int lane = blockIdx.x * LPB + l;
    const int b    = lane >> 8;          // H = 256
    const int hc   = lane & (Hn - 1);

    sel[tid] = fcur[tid * Bn + b];       // t = tid (0..511)
    int any = __syncthreads_or(sel[tid]);
    if (!any) return;                    // fs pre-zeroed upstream

    const float bt = beta[hc];
    const float* base = cur + (long long)(w * CLEN) * BH + lane;

    float m = 0.0f;
    #pragma unroll
    for (int j = 0; j < CLEN; j++) {
        float c = sel[w * CLEN + j] ? base[j * BH] : 0.0f;
        m = fmaf(bt, m, c);
    }
    S[w][l] = m;
    __syncthreads();

    if (w == 0) {
        float b2  = bt * bt;
        float b4  = b2 * b2;
        float b8  = b4 * b4;
        float b16 = b8 * b8;
        float b32 = b16 * b16;
        float c = 0.0f;
        #pragma unroll
        for (int k = 0; k < CHUNKS; k++) {
            Carry[k][l] = c;
            c = fmaf(b32, c, S[k][l]);
        }
    }
    __syncthreads();

    m = Carry[w][l];
    #pragma unroll
    for (int j = 0; j < CLEN; j++) {
        int t = w * CLEN + j;
        float c = sel[t] ? base[j * BH] : 0.0f;
        m = fmaf(bt, m, c);
        float s = (m > 1.0f) ? 1.0f : 0.0f;
        spk[(long long)t * BH + lane] = s;
        if (s != 0.0f) atomicOr(&fs[t * Bn + b], 1);
    }
}

// ---------------------------------------------------------------------------
// Vocab GEMM (output): C[Mn, Vn] = mask(A) @ Wout + bout. ALWAYS stores.
// ---------------------------------------------------------------------------
#define NTV 256

__global__ void __launch_bounds__(256)
vocab_kernel(const float* __restrict__ A,
             const float* __restrict__ W,
             const float* __restrict__ bias,
             float* __restrict__ C,
             const int* __restrict__ flags_in) {
    __shared__ int sflag[MT];
    const int bm = blockIdx.y * MT;
    const int bn = blockIdx.x * NTV;
    const int tid = threadIdx.x;

    if (tid < MT) sflag[tid] = flags_in[bm + tid];
    int anyflag = __syncthreads_or(tid < MT ? sflag[tid] : 0);

    if (!anyflag) {
        int c4 = (tid & 63) * 4;
        int r0 = tid >> 6;
        float4 bv = *reinterpret_cast<const float4*>(&bias[bn + c4]);
        #pragma unroll
        for (int r = r0; r < MT; r += 4)
            __stwt(reinterpret_cast<float4*>(&C[(long long)(bm + r)*Vn + bn + c4]), bv);
        return;
    }

    // dense fallback
    __shared__ __align__(16) float As[MT][KT + 1];
    __shared__ __align__(16) float Ws[KT][NTV + 4];

    const int ty = tid >> 4;
    const int tx = tid & 15;
    float acc[4][16];
    #pragma unroll
    for (int i = 0; i < 4; i++)
        #pragma unroll
        for (int j = 0; j < 16; j++) acc[i][j] = 0.0f;

    for (int k0 = 0; k0 < Hn; k0 += KT) {
        {
            int row = tid >> 2, kq = (tid & 3) * 4;
            float4 a4 = *reinterpret_cast<const float4*>(&A[(long long)(bm + row)*Hn + k0 + kq]);
            if (!sflag[row]) { a4.x = a4.y = a4.z = a4.w = 0.0f; }
            As[row][kq + 0] = a4.x; As[row][kq + 1] = a4.y;
            As[row][kq + 2] = a4.z; As[row][kq + 3] = a4.w;
        }
        #pragma unroll
        for (int it = 0; it < 4; it++) {
            int f = tid + it * 256;
            int kk = f >> 6;
            int nq = (f & 63) * 4;
            float4 w4 = *reinterpret_cast<const float4*>(&W[(long long)(k0 + kk)*Vn + bn + nq]);
            *reinterpret_cast<float4*>(&Ws[kk][nq]) = w4;
        }
        __syncthreads();

        #pragma unroll
        for (int k = 0; k < KT; k++) {
            float a0 = As[ty*4 + 0][k];
            float a1 = As[ty*4 + 1][k];
            float a2 = As[ty*4 + 2][k];
            float a3 = As[ty*4 + 3][k];
            #pragma unroll
            for (int jq = 0; jq < 4; jq++) {
                float4 wq = *reinterpret_cast<const float4*>(&Ws[k][tx*16 + jq*4]);
                float wv[4] = {wq.x, wq.y, wq.z, wq.w};
                #pragma unroll
                for (int j = 0; j < 4; j++) {
                    acc[0][jq*4 + j] = fmaf(a0, wv[j], acc[0][jq*4 + j]);
                    acc[1][jq*4 + j] = fmaf(a1, wv[j], acc[1][jq*4 + j]);
                    acc[2][jq*4 + j] = fmaf(a2, wv[j], acc[2][jq*4 + j]);
                    acc[3][jq*4 + j] = fmaf(a3, wv[j], acc[3][jq*4 + j]);
                }
            }
        }
        __syncthreads();
    }

    #pragma unroll
    for (int i = 0; i < 4; i++) {
        int row = bm + ty*4 + i;
        #pragma unroll
        for (int jq = 0; jq < 4; jq++) {
            float4 o;
            o.x = acc[i][jq*4 + 0] + bias[bn + tx*16 + jq*4 + 0];
            o.y = acc[i][jq*4 + 1] + bias[bn + tx*16 + jq*4 + 1];
            o.z = acc[i][jq*4 + 2] + bias[bn + tx*16 + jq*4 + 2];
            o.w = acc[i][jq*4 + 3] + bias[bn + tx*16 + jq*4 + 3];
            *reinterpret_cast<float4*>(&C[(long long)row*Vn + bn + tx*16 + jq*4]) = o;
        }
    }
}

// ---------------------------------------------------------------------------
// launch
// ---------------------------------------------------------------------------
extern "C" void kernel_launch(void* const* d_in, const int* in_sizes, int n_in,
                              void* d_out, int out_size) {
    const int*   tokens  = (const int*)  d_in[0];
    const float* tok_emb = (const float*)d_in[1];
    const float* pos_emb = (const float*)d_in[2];
    const float* Wq      = (const float*)d_in[3];
    const float* bq      = (const float*)d_in[4];
    const float* beta    = (const float*)d_in[5];
    const float* Wfc     = (const float*)d_in[6];
    const float* bfc     = (const float*)d_in[7];
    const float* Wout    = (const float*)d_in[8];
    const float* bout    = (const float*)d_in[9];
    float* out = (float*)d_out;

    float *cur, *spk, *h;
    int *fcur, *fs, *fh;
    cudaGetSymbolAddress((void**)&cur,  g_cur);
    cudaGetSymbolAddress((void**)&spk,  g_spk);
    cudaGetSymbolAddress((void**)&h,    g_h);
    cudaGetSymbolAddress((void**)&fcur, g_fcur);
    cudaGetSymbolAddress((void**)&fs,   g_fs);
    cudaGetSymbolAddress((void**)&fh,   g_fh);

    dim3 gsmall(Hn / NT, Mn / MT);   // (4, 64)

    // layer 0: fused embed + q-projection (dense, row-pair FFMA2)
    gemm_embed_kernel<<<gsmall, 128>>>(tokens, tok_emb, pos_emb,
                                       Wq, bq, cur, fcur, fs);
    scan_kernel<<<BH / LPB, 512>>>(cur, beta, spk, fcur, fs);
    gemm_internal_kernel<<<gsmall, 128>>>(spk, Wfc, bfc, h, /*relu=*/1,
                                          fs, fh, nullptr);

    // layers 1..2
    for (int l = 1; l < Ln; l++) {
        gemm_internal_kernel<<<gsmall, 128>>>(h, Wq + (long long)l*Hn*Hn,
                                              bq + l*Hn, cur, /*relu=*/0,
                                              fh, fcur, fs);
        scan_kernel<<<BH / LPB, 512>>>(cur, beta + l*Hn, spk, fcur, fs);
        gemm_internal_kernel<<<gsmall, 128>>>(spk, Wfc + (long long)l*Hn*Hn,
                                              bfc + l*Hn, h, /*relu=*/1,
                                              fs, fh, nullptr);
    }

    dim3 gbig(Vn / NTV, Mn / MT);    // (125, 64)
    vocab_kernel<<<gbig, 256>>>(h, Wout, bout, out, fh);
}